// round 10
// baseline (speedup 1.0000x reference)
#include <cuda_runtime.h>
#include <cuda_fp16.h>
#include <cstdint>

typedef unsigned short u16;
typedef unsigned long long u64;

// Problem constants
#define BB    8
#define NN    65536
#define NPTS  (BB*NN)           // 524288
#define GSIZE (1<<21)           // 128^3 cells per batch
#define GTOT  (BB*GSIZE)        // 16,777,216

// ---------------- device scratch (static, no allocation) ----------------
__device__ int      g_grid[GTOT];
__device__ int      g_bsum[4096];
__device__ int      g_Mb[BB];
__device__ int      g_nvalid;
__device__ int      g_code[NPTS];
__device__ int      g_inv[NPTS];
__device__ int      g_slotcode[NPTS];
__device__ float    g_cnt[NPTS];
__device__ float    g_vfeat[(size_t)NPTS*16];
__device__ int      g_nbr[(size_t)NPTS*27];   // TRANSPOSED: [ko][b*NN+slot]
__device__ float    g_h1[(size_t)NPTS*32];
__device__ float    g_h2[(size_t)NPTS*64];
__device__ float    g_h3[(size_t)NPTS*128];
__device__ unsigned g_obits[3];
__device__ double   g_sum[128], g_sumsq[128];
__device__ float    g_scale[128], g_shift[128];
// fp16 inputs per layer: voxel row = CIN u16
__device__ u16      g_x1[(size_t)NPTS*16];
__device__ u16      g_x2[(size_t)NPTS*32];
__device__ u16      g_x3[(size_t)NPTS*64];
// fp16 weights, pre-swizzled smem-image tiles: [27][COUT rows][64 u16 = 128B]
__device__ u16      g_w1[27*32*64];
__device__ u16      g_w2[27*64*64];
__device__ u16      g_w3[27*128*64];

// ---------------- ptx helpers ----------------
__device__ __forceinline__ uint32_t s2u(const void* p) {
    uint32_t a;
    asm("{ .reg .u64 t; cvta.to.shared.u64 t, %1; cvt.u32.u64 %0, t; }"
        : "=r"(a) : "l"(p));
    return a;
}
__device__ __forceinline__ void cpasync16(uint32_t dst, const void* src, uint32_t sz) {
    asm volatile("cp.async.cg.shared.global [%0], [%1], 16, %2;"
                 :: "r"(dst), "l"(src), "r"(sz) : "memory");
}
__device__ __forceinline__ void cpcommit() {
    asm volatile("cp.async.commit_group;" ::: "memory");
}
template <int N>
__device__ __forceinline__ void cpwait() {
    asm volatile("cp.async.wait_group %0;" :: "n"(N) : "memory");
}
__device__ __forceinline__ void ldmx4(uint32_t* r, uint32_t addr) {
    asm volatile("ldmatrix.sync.aligned.m8n8.x4.shared.b16 {%0,%1,%2,%3}, [%4];"
                 : "=r"(r[0]), "=r"(r[1]), "=r"(r[2]), "=r"(r[3]) : "r"(addr));
}
__device__ __forceinline__ void mma16816(float* d, const uint32_t* a,
                                         const uint32_t* b) {
    asm volatile(
        "mma.sync.aligned.m16n8k16.row.col.f32.f16.f16.f32 "
        "{%0,%1,%2,%3}, {%4,%5,%6,%7}, {%8,%9}, {%0,%1,%2,%3};"
        : "+f"(d[0]), "+f"(d[1]), "+f"(d[2]), "+f"(d[3])
        : "r"(a[0]), "r"(a[1]), "r"(a[2]), "r"(a[3]), "r"(b[0]), "r"(b[1]));
}
__device__ __forceinline__ uint32_t swz(uint32_t off) {
    return off ^ ((off >> 3) & 0x70);
}
__device__ __forceinline__ u16 f2h(float f) {
    __half h = __float2half_rn(f);
    return *reinterpret_cast<u16*>(&h);
}

// ---------------- prologue helpers ----------------
__device__ __forceinline__ int blockExclScan(int val, int &total, int nwarps) {
    int lane = threadIdx.x & 31, wid = threadIdx.x >> 5;
    int v = val;
#pragma unroll
    for (int o = 1; o < 32; o <<= 1) {
        int t = __shfl_up_sync(0xffffffffu, v, o);
        if (lane >= o) v += t;
    }
    __shared__ int ws[32];
    if (lane == 31) ws[wid] = v;
    __syncthreads();
    if (wid == 0) {
        int w = (lane < nwarps) ? ws[lane] : 0;
#pragma unroll
        for (int o = 1; o < 32; o <<= 1) {
            int t = __shfl_up_sync(0xffffffffu, w, o);
            if (lane >= o) w += t;
        }
        ws[lane] = w;
    }
    __syncthreads();
    int warpoff = wid ? ws[wid - 1] : 0;
    total = ws[nwarps - 1];
    return warpoff + v - val;
}

// ---------------- prologue kernels ----------------
__global__ void k_zero() {
    size_t i = (size_t)blockIdx.x * blockDim.x + threadIdx.x;
    size_t stride = (size_t)gridDim.x * blockDim.x;
    for (size_t j = i; j < (size_t)GTOT; j += stride) g_grid[j] = 0;
    for (size_t j = i; j < (size_t)NPTS; j += stride) g_cnt[j] = 0.f;
    for (size_t j = i; j < (size_t)NPTS * 16; j += stride) g_vfeat[j] = 0.f;
    if (i < 3) g_obits[i] = 0x7F7FFFFFu;
}

__global__ void k_min(const float* __restrict__ xyz) {
    float mn0 = 3.4e38f, mn1 = 3.4e38f, mn2 = 3.4e38f;
    for (int i = blockIdx.x * blockDim.x + threadIdx.x; i < NPTS;
         i += gridDim.x * blockDim.x) {
        mn0 = fminf(mn0, xyz[3 * i + 0]);
        mn1 = fminf(mn1, xyz[3 * i + 1]);
        mn2 = fminf(mn2, xyz[3 * i + 2]);
    }
#pragma unroll
    for (int o = 16; o; o >>= 1) {
        mn0 = fminf(mn0, __shfl_down_sync(0xffffffffu, mn0, o));
        mn1 = fminf(mn1, __shfl_down_sync(0xffffffffu, mn1, o));
        mn2 = fminf(mn2, __shfl_down_sync(0xffffffffu, mn2, o));
    }
    __shared__ float s[3][8];
    int lane = threadIdx.x & 31, wid = threadIdx.x >> 5;
    if (lane == 0) { s[0][wid] = mn0; s[1][wid] = mn1; s[2][wid] = mn2; }
    __syncthreads();
    if (threadIdx.x == 0) {
        float a = s[0][0], b = s[1][0], c = s[2][0];
        for (int w = 1; w < 8; w++) {
            a = fminf(a, s[0][w]); b = fminf(b, s[1][w]); c = fminf(c, s[2][w]);
        }
        atomicMin(&g_obits[0], __float_as_uint(a));
        atomicMin(&g_obits[1], __float_as_uint(b));
        atomicMin(&g_obits[2], __float_as_uint(c));
    }
}

__global__ void k_codes(const float* __restrict__ xyz) {
    int i = blockIdx.x * blockDim.x + threadIdx.x;
    if (i >= NPTS) return;
    int b = i / NN;
    float ox = __uint_as_float(g_obits[0]);
    float oy = __uint_as_float(g_obits[1]);
    float oz = __uint_as_float(g_obits[2]);
    int vx = (int)__fdiv_rn(xyz[3 * i + 0] - ox, 0.4f);
    int vy = (int)__fdiv_rn(xyz[3 * i + 1] - oy, 0.4f);
    int vz = (int)__fdiv_rn(xyz[3 * i + 2] - oz, 0.4f);
    vx = min(127, max(0, vx)); vy = min(127, max(0, vy)); vz = min(127, max(0, vz));
    int code = vx | (vy << 7) | (vz << 14);
    g_code[i] = code;
    g_grid[(size_t)b * GSIZE + code] = 1;
}

__global__ void k_scanA() {
    int base = blockIdx.x * 4096 + threadIdx.x * 4;
    int s = g_grid[base] + g_grid[base + 1] + g_grid[base + 2] + g_grid[base + 3];
    int tot;
    blockExclScan(s, tot, 32);
    if (threadIdx.x == 0) g_bsum[blockIdx.x] = tot;
}

__global__ void k_scanB() {
    int b = blockIdx.x, t = threadIdx.x;
    int v = g_bsum[b * 512 + t];
    int tot;
    int excl = blockExclScan(v, tot, 16);
    g_bsum[b * 512 + t] = excl;
    if (t == 511) g_Mb[b] = tot;
}

__global__ void k_sumMb() {
    if (threadIdx.x == 0) {
        int s = 0;
        for (int b = 0; b < BB; b++) s += g_Mb[b];
        g_nvalid = s;
    }
}

__global__ void k_scanC() {
    int blk = blockIdx.x;
    int b = blk >> 9;
    int cbase = (blk & 511) * 4096 + threadIdx.x * 4;
    size_t gbase = (size_t)b * GSIZE + cbase;
    int o0 = g_grid[gbase + 0], o1 = g_grid[gbase + 1];
    int o2 = g_grid[gbase + 2], o3 = g_grid[gbase + 3];
    int s = o0 + o1 + o2 + o3;
    int tot;
    int excl = blockExclScan(s, tot, 32);
    int run = g_bsum[blk] + excl;
    int occ[4] = {o0, o1, o2, o3};
#pragma unroll
    for (int j = 0; j < 4; j++) {
        if (occ[j]) {
            g_grid[gbase + j] = run;
            g_slotcode[b * NN + run] = cbase + j;
            run++;
        } else {
            g_grid[gbase + j] = -1;
        }
    }
}

__global__ void k_aggregate(const float* __restrict__ feat,
                            const float* __restrict__ mask) {
    int i = blockIdx.x * blockDim.x + threadIdx.x;
    if (i >= NPTS) return;
    int b = i / NN;
    int code = g_code[i];
    int slot = g_grid[(size_t)b * GSIZE + code];
    g_inv[i] = slot;
    float m = mask[i];
    if (m != 0.f) {
        int row = b * NN + slot;
        atomicAdd(&g_cnt[row], m);
        const float* f = feat + (size_t)i * 16;
        float* dst = g_vfeat + (size_t)row * 16;
#pragma unroll
        for (int c = 0; c < 16; c++) atomicAdd(&dst[c], f[c] * m);
    }
}

// normalize voxel features and emit fp16 rows for conv1
__global__ void k_vnorm() {
    int i = blockIdx.x * blockDim.x + threadIdx.x;
    if (i >= NPTS) return;
    int b = i / NN, slot = i - b * NN;
    if (slot >= g_Mb[b]) return;
    float inv = 1.f / fmaxf(g_cnt[i], 1.f);
    const float* r = g_vfeat + (size_t)i * 16;
    u16* dst = g_x1 + (size_t)i * 16;
#pragma unroll
    for (int q = 0; q < 4; q++) {
        float4 x = *reinterpret_cast<const float4*>(r + 4 * q);
        u16 h0 = f2h(x.x * inv), h1 = f2h(x.y * inv);
        u16 h2 = f2h(x.z * inv), h3 = f2h(x.w * inv);
        *reinterpret_cast<u64*>(dst + 4 * q) =
            (u64)h0 | ((u64)h1 << 16) | ((u64)h2 << 32) | ((u64)h3 << 48);
    }
}

__global__ void k_nbr() {
    int slot = blockIdx.x * blockDim.x + threadIdx.x;
    int b = blockIdx.y;
    if (slot >= g_Mb[b]) return;
    int code = g_slotcode[b * NN + slot];
    int x = code & 127, y = (code >> 7) & 127, z = code >> 14;
    const int* grid = g_grid + (size_t)b * GSIZE;
    int row = b * NN + slot;
    int ko = 0;
    for (int dz = -1; dz <= 1; dz++)
        for (int dy = -1; dy <= 1; dy++)
            for (int dx = -1; dx <= 1; dx++, ko++) {
                int nx = x + dx, ny = y + dy, nz = z + dz;
                int r = -1;
                if ((unsigned)nx < 128u && (unsigned)ny < 128u && (unsigned)nz < 128u)
                    r = grid[nx | (ny << 7) | (nz << 14)];
                g_nbr[(size_t)ko * NPTS + row] = r;   // transposed layout
            }
}

// ---------------- weight rounding into swizzled fp16 smem-image tiles -----
template <int CIN, int COUT>
__global__ void k_wsplit(const float* __restrict__ W, u16* __restrict__ Wout) {
    int i = blockIdx.x * blockDim.x + threadIdx.x;
    if (i >= 27 * COUT * CIN) return;
    int cil = i % CIN;
    int co = (i / CIN) % COUT;
    int ko = i / (CIN * COUT);
    float w = W[(ko * CIN + cil) * COUT + co];
    size_t base = (size_t)ko * (COUT * 64);
    uint32_t off = swz((uint32_t)(co * 128 + cil * 2));
    Wout[base + off / 2] = f2h(w);
}

// ---------------- BN+ReLU + fp16 cast of a feature map -------------------
template <int C>
__global__ void k_split(const float* __restrict__ in, u16* __restrict__ out) {
    int idx = blockIdx.x * blockDim.x + threadIdx.x;
    if (idx >= NPTS * (C / 4)) return;
    int v = idx / (C / 4);
    int q = idx - v * (C / 4);
    int c0 = 4 * q;
    float4 x = reinterpret_cast<const float4*>(in)[idx];
    x.x = fmaxf(fmaf(x.x, g_scale[c0 + 0], g_shift[c0 + 0]), 0.f);
    x.y = fmaxf(fmaf(x.y, g_scale[c0 + 1], g_shift[c0 + 1]), 0.f);
    x.z = fmaxf(fmaf(x.z, g_scale[c0 + 2], g_shift[c0 + 2]), 0.f);
    x.w = fmaxf(fmaf(x.w, g_scale[c0 + 3], g_shift[c0 + 3]), 0.f);
    u16 h0 = f2h(x.x), h1 = f2h(x.y), h2 = f2h(x.z), h3 = f2h(x.w);
    *reinterpret_cast<u64*>(out + (size_t)v * C + c0) =
        (u64)h0 | ((u64)h1 << 16) | ((u64)h2 << 32) | ((u64)h3 << 48);
}

// ---------------- cp.async-pipelined warp-MMA gather-conv, M=256 ----------
// 256-voxel tile per CTA; 8 warps each own 32 rows x full COUT. 2-deep
// cp.async pipeline. Single fp16 product: D += x*w.
template <int CIN, int COUT>
__global__ void __launch_bounds__(256, 2)
conv_pipe(const u16* __restrict__ X, float* __restrict__ fout,
          const u16* __restrict__ Wg, const float* __restrict__ bias) {
    constexpr int CK = CIN / 16;
    constexpr int NT = COUT / 8;
    constexpr int NP = NT / 2;
    constexpr int ATILE = 32768;         // 256 rows x 128B
    constexpr int BTILE = COUT * 128;    // fp16 w tile
    constexpr int BUFSZ = ATILE + BTILE;
    constexpr int RB = 2 * CIN;          // gmem bytes per voxel row
    constexpr int CPT = RB / 16;         // 16B chunks per row (1 thread/row)
    extern __shared__ char smem[];

    int blk = blockIdx.x;
    int b = blk >> 8, tilei = blk & 255;
    int Mb = g_Mb[b];
    int v0 = tilei * 256;
    if (v0 >= Mb) return;
    int tid = threadIdx.x, wid = tid >> 5, lane = tid & 31;

    uint32_t sbase = (s2u(smem) + 1023) & ~1023u;

    // staging: one thread per voxel row
    int gv = b * NN + v0 + tid;
    bool vok = (v0 + tid) < Mb;
    uint32_t arow = (uint32_t)tid * 128;

    // ldmatrix lane bases
    uint32_t a_off0 = (uint32_t)(wid * 32 + (lane & 15)) * 128 + (lane >> 4) * 16;
    uint32_t b_off0 = (uint32_t)((lane >> 4) * 8 + (lane & 7)) * 128 +
                      ((lane >> 3) & 1) * 16;

    float d[2][NT][4];
#pragma unroll
    for (int mt = 0; mt < 2; mt++)
#pragma unroll
        for (int nt = 0; nt < NT; nt++)
#pragma unroll
            for (int j = 0; j < 4; j++) d[mt][nt][j] = 0.f;

    const u16* Xb = X + (size_t)b * NN * CIN;

    auto stage = [&](int ko, int buf, int nbr) {
        uint32_t sB = sbase + buf * BUFSZ + ATILE;
        const char* wsrc = (const char*)Wg + (size_t)ko * BTILE;
#pragma unroll
        for (int e = 0; e < BTILE / 16 / 256; e++) {
            int idx = tid + e * 256;
            cpasync16(sB + idx * 16, wsrc + idx * 16, 16);
        }
        uint32_t sA = sbase + buf * BUFSZ;
        uint32_t sz = (nbr >= 0) ? 16u : 0u;
        const char* xs = (const char*)(Xb + (size_t)max(nbr, 0) * CIN);
#pragma unroll
        for (int j = 0; j < CPT; j++)
            cpasync16(sA + swz(arow + (uint32_t)j * 16), xs + j * 16, sz);
    };

    auto compute = [&](int buf) {
        uint32_t sA = sbase + buf * BUFSZ;
        uint32_t sB = sA + ATILE;
#pragma unroll
        for (int kc = 0; kc < CK; kc++) {
            uint32_t ah[2][4];
#pragma unroll
            for (int mt = 0; mt < 2; mt++)
                ldmx4(ah[mt], sA + swz(a_off0 + (uint32_t)mt * 2048 + kc * 32));
#pragma unroll
            for (int p = 0; p < NP; p++) {
                uint32_t bh[4];
                ldmx4(bh, sB + swz(b_off0 + p * 2048 + kc * 32));
#pragma unroll
                for (int mt = 0; mt < 2; mt++) {
                    mma16816(d[mt][2 * p],     ah[mt], bh);
                    mma16816(d[mt][2 * p + 1], ah[mt], bh + 2);
                }
            }
        }
    };

    int nbr_c = vok ? __ldg(&g_nbr[gv]) : -1;               // tap 0
    stage(0, 0, nbr_c);
    cpcommit();
    int nbr_n = vok ? __ldg(&g_nbr[(size_t)NPTS + gv]) : -1; // tap 1
    for (int ko = 0; ko < 27; ko++) {
        int nxt = ko + 1;
        if (nxt < 27) {
            stage(nxt, nxt & 1, nbr_n);
            cpcommit();
            nbr_n = (vok && nxt + 1 < 27)
                ? __ldg(&g_nbr[(size_t)(nxt + 1) * NPTS + gv]) : -1;
            cpwait<1>();
        } else {
            cpwait<0>();
        }
        __syncthreads();
        compute(ko & 1);
        __syncthreads();   // buffer (ko&1) free for restage at iter ko+1
    }

    // epilogue: D regs -> gmem (+bias)
    int col0 = (lane & 3) * 2;
#pragma unroll
    for (int mt = 0; mt < 2; mt++) {
        int m0 = v0 + wid * 32 + mt * 16 + (lane >> 2);
        bool ok0 = m0 < Mb, ok1 = (m0 + 8) < Mb;
        float* dst0 = fout + ((size_t)(b * NN + m0)) * COUT;
        float* dst1 = dst0 + (size_t)8 * COUT;
#pragma unroll
        for (int nt = 0; nt < NT; nt++) {
            int c = nt * 8 + col0;
            float bx = bias[c], by = bias[c + 1];
            if (ok0)
                *reinterpret_cast<float2*>(dst0 + c) =
                    make_float2(d[mt][nt][0] + bx, d[mt][nt][1] + by);
            if (ok1)
                *reinterpret_cast<float2*>(dst1 + c) =
                    make_float2(d[mt][nt][2] + bx, d[mt][nt][3] + by);
        }
    }
}

// ---------------- BN stats / finalize / output ---------------------------
__global__ void k_zero_stats() {
    int t = threadIdx.x;
    if (t < 128) { g_sum[t] = 0.0; g_sumsq[t] = 0.0; }
}

template <int COUT>
__global__ void k_stats(const float* __restrict__ f) {
    constexpr int RP = 256 / COUT;
    int b = blockIdx.y;
    int Mb = g_Mb[b];
    int tid = threadIdx.x;
    int c = tid % COUT, r0 = tid / COUT;
    float s = 0.f, s2 = 0.f;
    for (int v = blockIdx.x * RP + r0; v < Mb; v += gridDim.x * RP) {
        float x = f[((size_t)(b * NN + v)) * COUT + c];
        s += x;
        s2 = fmaf(x, x, s2);
    }
    __shared__ float sh[256], sh2[256];
    sh[tid] = s; sh2[tid] = s2;
    __syncthreads();
    for (int st = 128; st >= COUT; st >>= 1) {
        if (tid < st) { sh[tid] += sh[tid + st]; sh2[tid] += sh2[tid + st]; }
        __syncthreads();
    }
    if (tid < COUT) {
        atomicAdd(&g_sum[tid], (double)sh[tid]);
        atomicAdd(&g_sumsq[tid], (double)sh2[tid]);
    }
}

template <int COUT>
__global__ void k_finalize(const float* __restrict__ gamma,
                           const float* __restrict__ beta) {
    int c = threadIdx.x;
    if (c >= COUT) return;
    double n = (double)g_nvalid;
    if (n < 1.0) n = 1.0;
    double mean = g_sum[c] / n;
    double var = g_sumsq[c] / n - mean * mean;
    if (var < 0.0) var = 0.0;
    float a = (float)((double)gamma[c] / sqrt(var + 1e-5));
    g_scale[c] = a;
    g_shift[c] = beta[c] - (float)mean * a;
}

__global__ void k_final(const float* __restrict__ mask, float* __restrict__ out) {
    size_t e = (size_t)blockIdx.x * blockDim.x + threadIdx.x;  // per float4
    if (e >= (size_t)NPTS * 32) return;
    int i = (int)(e >> 5);
    int c4 = (int)(e & 31);
    int b = i / NN;
    int slot = g_inv[i];
    const float4* src = reinterpret_cast<const float4*>(
        g_h3 + ((size_t)(b * NN + slot)) * 128) + c4;
    float4 h = *src;
    float m = mask[i];
    int c = c4 * 4;
    float4 y;
    y.x = fmaxf(fmaf(h.x, g_scale[c + 0], g_shift[c + 0]), 0.f) * m;
    y.y = fmaxf(fmaf(h.y, g_scale[c + 1], g_shift[c + 1]), 0.f) * m;
    y.z = fmaxf(fmaf(h.z, g_scale[c + 2], g_shift[c + 2]), 0.f) * m;
    y.w = fmaxf(fmaf(h.w, g_scale[c + 3], g_shift[c + 3]), 0.f) * m;
    reinterpret_cast<float4*>(out)[e] = y;
}

// ---------------- host ----------------
extern "C" void kernel_launch(void* const* d_in, const int* in_sizes, int n_in,
                              void* d_out, int out_size) {
    const float* xyz  = (const float*)d_in[0];
    const float* feat = (const float*)d_in[1];
    const float* mask = (const float*)d_in[2];
    const float* W1 = (const float*)d_in[3];
    const float* b1 = (const float*)d_in[4];
    const float* g1 = (const float*)d_in[5];
    const float* be1 = (const float*)d_in[6];
    const float* W2 = (const float*)d_in[7];
    const float* b2 = (const float*)d_in[8];
    const float* g2 = (const float*)d_in[9];
    const float* be2 = (const float*)d_in[10];
    const float* W3 = (const float*)d_in[11];
    const float* b3 = (const float*)d_in[12];
    const float* g3 = (const float*)d_in[13];
    const float* be3 = (const float*)d_in[14];
    float* out = (float*)d_out;

    void *p1, *p2, *p3, *x1, *x2, *x3, *w1, *w2, *w3;
    cudaGetSymbolAddress(&p1, g_h1);
    cudaGetSymbolAddress(&p2, g_h2);
    cudaGetSymbolAddress(&p3, g_h3);
    cudaGetSymbolAddress(&x1, g_x1);
    cudaGetSymbolAddress(&x2, g_x2);
    cudaGetSymbolAddress(&x3, g_x3);
    cudaGetSymbolAddress(&w1, g_w1);
    cudaGetSymbolAddress(&w2, g_w2);
    cudaGetSymbolAddress(&w3, g_w3);

    // dynamic smem: 1KB align slack + 2 pipeline buffers
    int sm1 = 1024 + 2 * (32768 + 32 * 128);    // 74752
    int sm2 = 1024 + 2 * (32768 + 64 * 128);    // 82944
    int sm3 = 1024 + 2 * (32768 + 128 * 128);   // 99328
    cudaFuncSetAttribute(conv_pipe<16, 32>,
                         cudaFuncAttributeMaxDynamicSharedMemorySize, sm1);
    cudaFuncSetAttribute(conv_pipe<32, 64>,
                         cudaFuncAttributeMaxDynamicSharedMemorySize, sm2);
    cudaFuncSetAttribute(conv_pipe<64, 128>,
                         cudaFuncAttributeMaxDynamicSharedMemorySize, sm3);

    k_zero<<<2048, 256>>>();
    k_wsplit<16, 32><<<(27 * 32 * 16 + 255) / 256, 256>>>(W1, (u16*)w1);
    k_wsplit<32, 64><<<(27 * 64 * 32 + 255) / 256, 256>>>(W2, (u16*)w2);
    k_wsplit<64, 128><<<(27 * 128 * 64 + 255) / 256, 256>>>(W3, (u16*)w3);
    k_min<<<512, 256>>>(xyz);
    k_codes<<<NPTS / 256, 256>>>(xyz);
    k_scanA<<<4096, 1024>>>();
    k_scanB<<<8, 512>>>();
    k_sumMb<<<1, 32>>>();
    k_scanC<<<4096, 1024>>>();
    k_aggregate<<<NPTS / 256, 256>>>(feat, mask);
    k_vnorm<<<NPTS / 256, 256>>>();
    k_nbr<<<dim3(NN / 128, BB), 128>>>();

    // layer 1: x1(16, fp16) -> h1(32)
    conv_pipe<16, 32><<<BB * 256, 256, sm1>>>((const u16*)x1, (float*)p1,
                                              (const u16*)w1, b1);
    k_zero_stats<<<1, 128>>>();
    k_stats<32><<<dim3(64, BB), 256>>>((const float*)p1);
    k_finalize<32><<<1, 32>>>(g1, be1);
    k_split<32><<<(NPTS * 8 + 255) / 256, 256>>>((const float*)p1, (u16*)x2);

    // layer 2: x2(32, fp16) -> h2(64)
    conv_pipe<32, 64><<<BB * 256, 256, sm2>>>((const u16*)x2, (float*)p2,
                                              (const u16*)w2, b2);
    k_zero_stats<<<1, 128>>>();
    k_stats<64><<<dim3(64, BB), 256>>>((const float*)p2);
    k_finalize<64><<<1, 64>>>(g2, be2);
    k_split<64><<<(NPTS * 16 + 255) / 256, 256>>>((const float*)p2, (u16*)x3);

    // layer 3: x3(64, fp16) -> h3(128)
    conv_pipe<64, 128><<<BB * 256, 256, sm3>>>((const u16*)x3, (float*)p3,
                                               (const u16*)w3, b3);
    k_zero_stats<<<1, 128>>>();
    k_stats<128><<<dim3(64, BB), 256>>>((const float*)p3);
    k_finalize<128><<<1, 128>>>(g3, be3);

    // scatter: out[point] = relu(bn3(h3[inv])) * mask
    k_final<<<(NPTS * 32 + 255) / 256, 256>>>(mask, out);
}

// round 12
// speedup vs baseline: 1.5929x; 1.5929x over previous
#include <cuda_runtime.h>
#include <cuda_fp16.h>
#include <cstdint>

typedef unsigned short u16;
typedef unsigned long long u64;

// Problem constants
#define BB    8
#define NN    65536
#define NPTS  (BB*NN)           // 524288
#define GSIZE (1<<21)           // 128^3 cells per batch
#define GTOT  (BB*GSIZE)        // 16,777,216

// ---------------- device scratch (static, no allocation) ----------------
__device__ int      g_grid[GTOT];
__device__ int      g_bsum[4096];
__device__ int      g_Mb[BB];
__device__ int      g_nvalid;
__device__ int      g_code[NPTS];
__device__ int      g_inv[NPTS];
__device__ int      g_slotcode[NPTS];
__device__ float    g_cnt[NPTS];
__device__ float    g_vfeat[(size_t)NPTS*16];
__device__ int      g_nbr[(size_t)NPTS*27];   // TRANSPOSED: [ko][b*NN+slot]
__device__ float    g_h1[(size_t)NPTS*32];
__device__ float    g_h2[(size_t)NPTS*64];
__device__ float    g_h3[(size_t)NPTS*128];
__device__ unsigned g_obits[3];
__device__ double   g_sum[128], g_sumsq[128];
__device__ float    g_scale[128], g_shift[128];
// fp16 inputs per layer: voxel row = CIN u16
__device__ u16      g_x1[(size_t)NPTS*16];
__device__ u16      g_x2[(size_t)NPTS*32];
__device__ u16      g_x3[(size_t)NPTS*64];
// fp16 weights, pre-swizzled smem-image tiles: [27][COUT rows][64 u16 = 128B]
__device__ u16      g_w1[27*32*64];
__device__ u16      g_w2[27*64*64];
__device__ u16      g_w3[27*128*64];

// ---------------- ptx helpers ----------------
__device__ __forceinline__ uint32_t s2u(const void* p) {
    uint32_t a;
    asm("{ .reg .u64 t; cvta.to.shared.u64 t, %1; cvt.u32.u64 %0, t; }"
        : "=r"(a) : "l"(p));
    return a;
}
__device__ __forceinline__ void cpasync16(uint32_t dst, const void* src, uint32_t sz) {
    asm volatile("cp.async.cg.shared.global [%0], [%1], 16, %2;"
                 :: "r"(dst), "l"(src), "r"(sz) : "memory");
}
__device__ __forceinline__ void cpcommit() {
    asm volatile("cp.async.commit_group;" ::: "memory");
}
template <int N>
__device__ __forceinline__ void cpwait() {
    asm volatile("cp.async.wait_group %0;" :: "n"(N) : "memory");
}
__device__ __forceinline__ void ldmx4(uint32_t* r, uint32_t addr) {
    asm volatile("ldmatrix.sync.aligned.m8n8.x4.shared.b16 {%0,%1,%2,%3}, [%4];"
                 : "=r"(r[0]), "=r"(r[1]), "=r"(r[2]), "=r"(r[3]) : "r"(addr));
}
__device__ __forceinline__ void mma16816(float* d, const uint32_t* a,
                                         const uint32_t* b) {
    asm volatile(
        "mma.sync.aligned.m16n8k16.row.col.f32.f16.f16.f32 "
        "{%0,%1,%2,%3}, {%4,%5,%6,%7}, {%8,%9}, {%0,%1,%2,%3};"
        : "+f"(d[0]), "+f"(d[1]), "+f"(d[2]), "+f"(d[3])
        : "r"(a[0]), "r"(a[1]), "r"(a[2]), "r"(a[3]), "r"(b[0]), "r"(b[1]));
}
__device__ __forceinline__ uint32_t swz(uint32_t off) {
    return off ^ ((off >> 3) & 0x70);
}
__device__ __forceinline__ u16 f2h(float f) {
    __half h = __float2half_rn(f);
    return *reinterpret_cast<u16*>(&h);
}

// ---------------- prologue helpers ----------------
__device__ __forceinline__ int blockExclScan(int val, int &total, int nwarps) {
    int lane = threadIdx.x & 31, wid = threadIdx.x >> 5;
    int v = val;
#pragma unroll
    for (int o = 1; o < 32; o <<= 1) {
        int t = __shfl_up_sync(0xffffffffu, v, o);
        if (lane >= o) v += t;
    }
    __shared__ int ws[32];
    if (lane == 31) ws[wid] = v;
    __syncthreads();
    if (wid == 0) {
        int w = (lane < nwarps) ? ws[lane] : 0;
#pragma unroll
        for (int o = 1; o < 32; o <<= 1) {
            int t = __shfl_up_sync(0xffffffffu, w, o);
            if (lane >= o) w += t;
        }
        ws[lane] = w;
    }
    __syncthreads();
    int warpoff = wid ? ws[wid - 1] : 0;
    total = ws[nwarps - 1];
    return warpoff + v - val;
}

// ---------------- prologue kernels ----------------
__global__ void k_zero() {
    size_t i = (size_t)blockIdx.x * blockDim.x + threadIdx.x;
    size_t stride = (size_t)gridDim.x * blockDim.x;
    for (size_t j = i; j < (size_t)GTOT; j += stride) g_grid[j] = 0;
    for (size_t j = i; j < (size_t)NPTS; j += stride) g_cnt[j] = 0.f;
    for (size_t j = i; j < (size_t)NPTS * 16; j += stride) g_vfeat[j] = 0.f;
    if (i < 3) g_obits[i] = 0x7F7FFFFFu;
}

__global__ void k_min(const float* __restrict__ xyz) {
    float mn0 = 3.4e38f, mn1 = 3.4e38f, mn2 = 3.4e38f;
    for (int i = blockIdx.x * blockDim.x + threadIdx.x; i < NPTS;
         i += gridDim.x * blockDim.x) {
        mn0 = fminf(mn0, xyz[3 * i + 0]);
        mn1 = fminf(mn1, xyz[3 * i + 1]);
        mn2 = fminf(mn2, xyz[3 * i + 2]);
    }
#pragma unroll
    for (int o = 16; o; o >>= 1) {
        mn0 = fminf(mn0, __shfl_down_sync(0xffffffffu, mn0, o));
        mn1 = fminf(mn1, __shfl_down_sync(0xffffffffu, mn1, o));
        mn2 = fminf(mn2, __shfl_down_sync(0xffffffffu, mn2, o));
    }
    __shared__ float s[3][8];
    int lane = threadIdx.x & 31, wid = threadIdx.x >> 5;
    if (lane == 0) { s[0][wid] = mn0; s[1][wid] = mn1; s[2][wid] = mn2; }
    __syncthreads();
    if (threadIdx.x == 0) {
        float a = s[0][0], b = s[1][0], c = s[2][0];
        for (int w = 1; w < 8; w++) {
            a = fminf(a, s[0][w]); b = fminf(b, s[1][w]); c = fminf(c, s[2][w]);
        }
        atomicMin(&g_obits[0], __float_as_uint(a));
        atomicMin(&g_obits[1], __float_as_uint(b));
        atomicMin(&g_obits[2], __float_as_uint(c));
    }
}

__global__ void k_codes(const float* __restrict__ xyz) {
    int i = blockIdx.x * blockDim.x + threadIdx.x;
    if (i >= NPTS) return;
    int b = i / NN;
    float ox = __uint_as_float(g_obits[0]);
    float oy = __uint_as_float(g_obits[1]);
    float oz = __uint_as_float(g_obits[2]);
    int vx = (int)__fdiv_rn(xyz[3 * i + 0] - ox, 0.4f);
    int vy = (int)__fdiv_rn(xyz[3 * i + 1] - oy, 0.4f);
    int vz = (int)__fdiv_rn(xyz[3 * i + 2] - oz, 0.4f);
    vx = min(127, max(0, vx)); vy = min(127, max(0, vy)); vz = min(127, max(0, vz));
    int code = vx | (vy << 7) | (vz << 14);
    g_code[i] = code;
    g_grid[(size_t)b * GSIZE + code] = 1;
}

__global__ void k_scanA() {
    int base = blockIdx.x * 4096 + threadIdx.x * 4;
    int s = g_grid[base] + g_grid[base + 1] + g_grid[base + 2] + g_grid[base + 3];
    int tot;
    blockExclScan(s, tot, 32);
    if (threadIdx.x == 0) g_bsum[blockIdx.x] = tot;
}

__global__ void k_scanB() {
    int b = blockIdx.x, t = threadIdx.x;
    int v = g_bsum[b * 512 + t];
    int tot;
    int excl = blockExclScan(v, tot, 16);
    g_bsum[b * 512 + t] = excl;
    if (t == 511) g_Mb[b] = tot;
}

__global__ void k_sumMb() {
    if (threadIdx.x == 0) {
        int s = 0;
        for (int b = 0; b < BB; b++) s += g_Mb[b];
        g_nvalid = s;
    }
}

__global__ void k_scanC() {
    int blk = blockIdx.x;
    int b = blk >> 9;
    int cbase = (blk & 511) * 4096 + threadIdx.x * 4;
    size_t gbase = (size_t)b * GSIZE + cbase;
    int o0 = g_grid[gbase + 0], o1 = g_grid[gbase + 1];
    int o2 = g_grid[gbase + 2], o3 = g_grid[gbase + 3];
    int s = o0 + o1 + o2 + o3;
    int tot;
    int excl = blockExclScan(s, tot, 32);
    int run = g_bsum[blk] + excl;
    int occ[4] = {o0, o1, o2, o3};
#pragma unroll
    for (int j = 0; j < 4; j++) {
        if (occ[j]) {
            g_grid[gbase + j] = run;
            g_slotcode[b * NN + run] = cbase + j;
            run++;
        } else {
            g_grid[gbase + j] = -1;
        }
    }
}

__global__ void k_aggregate(const float* __restrict__ feat,
                            const float* __restrict__ mask) {
    int i = blockIdx.x * blockDim.x + threadIdx.x;
    if (i >= NPTS) return;
    int b = i / NN;
    int code = g_code[i];
    int slot = g_grid[(size_t)b * GSIZE + code];
    g_inv[i] = slot;
    float m = mask[i];
    if (m != 0.f) {
        int row = b * NN + slot;
        atomicAdd(&g_cnt[row], m);
        const float* f = feat + (size_t)i * 16;
        float* dst = g_vfeat + (size_t)row * 16;
#pragma unroll
        for (int c = 0; c < 16; c++) atomicAdd(&dst[c], f[c] * m);
    }
}

// normalize voxel features and emit fp16 rows for conv1
__global__ void k_vnorm() {
    int i = blockIdx.x * blockDim.x + threadIdx.x;
    if (i >= NPTS) return;
    int b = i / NN, slot = i - b * NN;
    if (slot >= g_Mb[b]) return;
    float inv = 1.f / fmaxf(g_cnt[i], 1.f);
    const float* r = g_vfeat + (size_t)i * 16;
    u16* dst = g_x1 + (size_t)i * 16;
#pragma unroll
    for (int q = 0; q < 4; q++) {
        float4 x = *reinterpret_cast<const float4*>(r + 4 * q);
        u16 h0 = f2h(x.x * inv), h1 = f2h(x.y * inv);
        u16 h2 = f2h(x.z * inv), h3 = f2h(x.w * inv);
        *reinterpret_cast<u64*>(dst + 4 * q) =
            (u64)h0 | ((u64)h1 << 16) | ((u64)h2 << 32) | ((u64)h3 << 48);
    }
}

__global__ void k_nbr() {
    int slot = blockIdx.x * blockDim.x + threadIdx.x;
    int b = blockIdx.y;
    if (slot >= g_Mb[b]) return;
    int code = g_slotcode[b * NN + slot];
    int x = code & 127, y = (code >> 7) & 127, z = code >> 14;
    const int* grid = g_grid + (size_t)b * GSIZE;
    int row = b * NN + slot;
    int ko = 0;
    for (int dz = -1; dz <= 1; dz++)
        for (int dy = -1; dy <= 1; dy++)
            for (int dx = -1; dx <= 1; dx++, ko++) {
                int nx = x + dx, ny = y + dy, nz = z + dz;
                int r = -1;
                if ((unsigned)nx < 128u && (unsigned)ny < 128u && (unsigned)nz < 128u)
                    r = grid[nx | (ny << 7) | (nz << 14)];
                g_nbr[(size_t)ko * NPTS + row] = r;   // transposed layout
            }
}

// ---------------- weight rounding into swizzled fp16 smem-image tiles -----
template <int CIN, int COUT>
__global__ void k_wsplit(const float* __restrict__ W, u16* __restrict__ Wout) {
    int i = blockIdx.x * blockDim.x + threadIdx.x;
    if (i >= 27 * COUT * CIN) return;
    int cil = i % CIN;
    int co = (i / CIN) % COUT;
    int ko = i / (CIN * COUT);
    float w = W[(ko * CIN + cil) * COUT + co];
    size_t base = (size_t)ko * (COUT * 64);
    uint32_t off = swz((uint32_t)(co * 128 + cil * 2));
    Wout[base + off / 2] = f2h(w);
}

// ---------------- BN+ReLU + fp16 cast of a feature map -------------------
template <int C>
__global__ void k_split(const float* __restrict__ in, u16* __restrict__ out) {
    int idx = blockIdx.x * blockDim.x + threadIdx.x;
    if (idx >= NPTS * (C / 4)) return;
    int v = idx / (C / 4);
    int q = idx - v * (C / 4);
    int c0 = 4 * q;
    float4 x = reinterpret_cast<const float4*>(in)[idx];
    x.x = fmaxf(fmaf(x.x, g_scale[c0 + 0], g_shift[c0 + 0]), 0.f);
    x.y = fmaxf(fmaf(x.y, g_scale[c0 + 1], g_shift[c0 + 1]), 0.f);
    x.z = fmaxf(fmaf(x.z, g_scale[c0 + 2], g_shift[c0 + 2]), 0.f);
    x.w = fmaxf(fmaf(x.w, g_scale[c0 + 3], g_shift[c0 + 3]), 0.f);
    u16 h0 = f2h(x.x), h1 = f2h(x.y), h2 = f2h(x.z), h3 = f2h(x.w);
    *reinterpret_cast<u64*>(out + (size_t)v * C + c0) =
        (u64)h0 | ((u64)h1 << 16) | ((u64)h2 << 32) | ((u64)h3 << 48);
}

// ---------------- cp.async-pipelined warp-MMA gather-conv, M=256 ----------
// 256-voxel tile per CTA; 8 warps each own 32 rows x full COUT. BUFN-deep
// cp.async buffer ring (stage up to BUFN-1 taps ahead). Single fp16 product.
template <int CIN, int COUT, int BUFN, int OCC>
__global__ void __launch_bounds__(256, OCC)
conv_pipe(const u16* __restrict__ X, float* __restrict__ fout,
          const u16* __restrict__ Wg, const float* __restrict__ bias) {
    constexpr int CK = CIN / 16;
    constexpr int NT = COUT / 8;
    constexpr int NP = NT / 2;
    constexpr int ATILE = 32768;         // 256 rows x 128B
    constexpr int BTILE = COUT * 128;    // fp16 w tile
    constexpr int BUFSZ = ATILE + BTILE;
    constexpr int CPT = (2 * CIN) / 16;  // 16B chunks per row (1 thread/row)
    extern __shared__ char smem[];

    int blk = blockIdx.x;
    int b = blk >> 8, tilei = blk & 255;
    int Mb = g_Mb[b];
    int v0 = tilei * 256;
    if (v0 >= Mb) return;
    int tid = threadIdx.x, wid = tid >> 5, lane = tid & 31;

    uint32_t sbase = (s2u(smem) + 1023) & ~1023u;

    // staging: one thread per voxel row
    int gv = b * NN + v0 + tid;
    bool vok = (v0 + tid) < Mb;
    uint32_t arow = (uint32_t)tid * 128;

    // ldmatrix lane bases
    uint32_t a_off0 = (uint32_t)(wid * 32 + (lane & 15)) * 128 + (lane >> 4) * 16;
    uint32_t b_off0 = (uint32_t)((lane >> 4) * 8 + (lane & 7)) * 128 +
                      ((lane >> 3) & 1) * 16;

    float d[2][NT][4];
#pragma unroll
    for (int mt = 0; mt < 2; mt++)
#pragma unroll
        for (int nt = 0; nt < NT; nt++)
#pragma unroll
            for (int j = 0; j < 4; j++) d[mt][nt][j] = 0.f;

    const u16* Xb = X + (size_t)b * NN * CIN;

    auto stage = [&](int ko, int buf, int nbr) {
        uint32_t sB = sbase + buf * BUFSZ + ATILE;
        const char* wsrc = (const char*)Wg + (size_t)ko * BTILE;
#pragma unroll
        for (int e = 0; e < BTILE / 16 / 256; e++) {
            int idx = tid + e * 256;
            cpasync16(sB + idx * 16, wsrc + idx * 16, 16);
        }
        uint32_t sA = sbase + buf * BUFSZ;
        uint32_t sz = (nbr >= 0) ? 16u : 0u;
        const char* xs = (const char*)(Xb + (size_t)max(nbr, 0) * CIN);
#pragma unroll
        for (int j = 0; j < CPT; j++)
            cpasync16(sA + swz(arow + (uint32_t)j * 16), xs + j * 16, sz);
    };

    auto compute = [&](int buf) {
        uint32_t sA = sbase + buf * BUFSZ;
        uint32_t sB = sA + ATILE;
#pragma unroll
        for (int kc = 0; kc < CK; kc++) {
            uint32_t ah[2][4];
#pragma unroll
            for (int mt = 0; mt < 2; mt++)
                ldmx4(ah[mt], sA + swz(a_off0 + (uint32_t)mt * 2048 + kc * 32));
#pragma unroll
            for (int p = 0; p < NP; p++) {
                uint32_t bh[4];
                ldmx4(bh, sB + swz(b_off0 + p * 2048 + kc * 32));
#pragma unroll
                for (int mt = 0; mt < 2; mt++) {
                    mma16816(d[mt][2 * p],     ah[mt], bh);
                    mma16816(d[mt][2 * p + 1], ah[mt], bh + 2);
                }
            }
        }
    };

    // prologue: stage taps 0..BUFN-2, one commit group each
#pragma unroll
    for (int t = 0; t < BUFN - 1; t++) {
        int nbr = vok ? __ldg(&g_nbr[(size_t)t * NPTS + gv]) : -1;
        stage(t, t, nbr);
        cpcommit();
    }
    int nbr_n = vok ? __ldg(&g_nbr[(size_t)(BUFN - 1) * NPTS + gv]) : -1;

    for (int ko = 0; ko < 27; ko++) {
        int nxt = ko + BUFN - 1;
        if (nxt < 27) stage(nxt, nxt % BUFN, nbr_n);
        cpcommit();   // empty group when nxt >= 27 keeps the ring accounting exact
        nbr_n = (vok && nxt + 1 < 27)
            ? __ldg(&g_nbr[(size_t)(nxt + 1) * NPTS + gv]) : -1;
        cpwait<BUFN - 1>();   // tap ko's group complete
        __syncthreads();
        compute(ko % BUFN);
        __syncthreads();      // buffer (ko%BUFN) free for restage
    }

    // epilogue: D regs -> gmem (+bias)
    int col0 = (lane & 3) * 2;
#pragma unroll
    for (int mt = 0; mt < 2; mt++) {
        int m0 = v0 + wid * 32 + mt * 16 + (lane >> 2);
        bool ok0 = m0 < Mb, ok1 = (m0 + 8) < Mb;
        float* dst0 = fout + ((size_t)(b * NN + m0)) * COUT;
        float* dst1 = dst0 + (size_t)8 * COUT;
#pragma unroll
        for (int nt = 0; nt < NT; nt++) {
            int c = nt * 8 + col0;
            float bx = bias[c], by = bias[c + 1];
            if (ok0)
                *reinterpret_cast<float2*>(dst0 + c) =
                    make_float2(d[mt][nt][0] + bx, d[mt][nt][1] + by);
            if (ok1)
                *reinterpret_cast<float2*>(dst1 + c) =
                    make_float2(d[mt][nt][2] + bx, d[mt][nt][3] + by);
        }
    }
}

// ---------------- BN stats / finalize / output ---------------------------
__global__ void k_zero_stats() {
    int t = threadIdx.x;
    if (t < 128) { g_sum[t] = 0.0; g_sumsq[t] = 0.0; }
}

template <int COUT>
__global__ void k_stats(const float* __restrict__ f) {
    constexpr int RP = 256 / COUT;
    int b = blockIdx.y;
    int Mb = g_Mb[b];
    int tid = threadIdx.x;
    int c = tid % COUT, r0 = tid / COUT;
    float s = 0.f, s2 = 0.f;
    for (int v = blockIdx.x * RP + r0; v < Mb; v += gridDim.x * RP) {
        float x = f[((size_t)(b * NN + v)) * COUT + c];
        s += x;
        s2 = fmaf(x, x, s2);
    }
    __shared__ float sh[256], sh2[256];
    sh[tid] = s; sh2[tid] = s2;
    __syncthreads();
    for (int st = 128; st >= COUT; st >>= 1) {
        if (tid < st) { sh[tid] += sh[tid + st]; sh2[tid] += sh2[tid + st]; }
        __syncthreads();
    }
    if (tid < COUT) {
        atomicAdd(&g_sum[tid], (double)sh[tid]);
        atomicAdd(&g_sumsq[tid], (double)sh2[tid]);
    }
}

template <int COUT>
__global__ void k_finalize(const float* __restrict__ gamma,
                           const float* __restrict__ beta) {
    int c = threadIdx.x;
    if (c >= COUT) return;
    double n = (double)g_nvalid;
    if (n < 1.0) n = 1.0;
    double mean = g_sum[c] / n;
    double var = g_sumsq[c] / n - mean * mean;
    if (var < 0.0) var = 0.0;
    float a = (float)((double)gamma[c] / sqrt(var + 1e-5));
    g_scale[c] = a;
    g_shift[c] = beta[c] - (float)mean * a;
}

__global__ void k_final(const float* __restrict__ mask, float* __restrict__ out) {
    size_t e = (size_t)blockIdx.x * blockDim.x + threadIdx.x;  // per float4
    if (e >= (size_t)NPTS * 32) return;
    int i = (int)(e >> 5);
    int c4 = (int)(e & 31);
    int b = i / NN;
    int slot = g_inv[i];
    const float4* src = reinterpret_cast<const float4*>(
        g_h3 + ((size_t)(b * NN + slot)) * 128) + c4;
    float4 h = *src;
    float m = mask[i];
    int c = c4 * 4;
    float4 y;
    y.x = fmaxf(fmaf(h.x, g_scale[c + 0], g_shift[c + 0]), 0.f) * m;
    y.y = fmaxf(fmaf(h.y, g_scale[c + 1], g_shift[c + 1]), 0.f) * m;
    y.z = fmaxf(fmaf(h.z, g_scale[c + 2], g_shift[c + 2]), 0.f) * m;
    y.w = fmaxf(fmaf(h.w, g_scale[c + 3], g_shift[c + 3]), 0.f) * m;
    reinterpret_cast<float4*>(out)[e] = y;
}

// ---------------- host ----------------
extern "C" void kernel_launch(void* const* d_in, const int* in_sizes, int n_in,
                              void* d_out, int out_size) {
    const float* xyz  = (const float*)d_in[0];
    const float* feat = (const float*)d_in[1];
    const float* mask = (const float*)d_in[2];
    const float* W1 = (const float*)d_in[3];
    const float* b1 = (const float*)d_in[4];
    const float* g1 = (const float*)d_in[5];
    const float* be1 = (const float*)d_in[6];
    const float* W2 = (const float*)d_in[7];
    const float* b2 = (const float*)d_in[8];
    const float* g2 = (const float*)d_in[9];
    const float* be2 = (const float*)d_in[10];
    const float* W3 = (const float*)d_in[11];
    const float* b3 = (const float*)d_in[12];
    const float* g3 = (const float*)d_in[13];
    const float* be3 = (const float*)d_in[14];
    float* out = (float*)d_out;

    void *p1, *p2, *p3, *x1, *x2, *x3, *w1, *w2, *w3;
    cudaGetSymbolAddress(&p1, g_h1);
    cudaGetSymbolAddress(&p2, g_h2);
    cudaGetSymbolAddress(&p3, g_h3);
    cudaGetSymbolAddress(&x1, g_x1);
    cudaGetSymbolAddress(&x2, g_x2);
    cudaGetSymbolAddress(&x3, g_x3);
    cudaGetSymbolAddress(&w1, g_w1);
    cudaGetSymbolAddress(&w2, g_w2);
    cudaGetSymbolAddress(&w3, g_w3);

    // dynamic smem: 1KB align slack + BUFN pipeline buffers
    int sm1 = 1024 + 2 * (32768 + 32 * 128);    // 74752  (BUFN=2, occ2)
    int sm2 = 1024 + 2 * (32768 + 64 * 128);    // 82944  (BUFN=2, occ2)
    int sm3 = 1024 + 4 * (32768 + 128 * 128);   // 197632 (BUFN=4, occ1)
    cudaFuncSetAttribute(conv_pipe<16, 32, 2, 2>,
                         cudaFuncAttributeMaxDynamicSharedMemorySize, sm1);
    cudaFuncSetAttribute(conv_pipe<32, 64, 2, 2>,
                         cudaFuncAttributeMaxDynamicSharedMemorySize, sm2);
    cudaFuncSetAttribute(conv_pipe<64, 128, 4, 1>,
                         cudaFuncAttributeMaxDynamicSharedMemorySize, sm3);

    k_zero<<<2048, 256>>>();
    k_wsplit<16, 32><<<(27 * 32 * 16 + 255) / 256, 256>>>(W1, (u16*)w1);
    k_wsplit<32, 64><<<(27 * 64 * 32 + 255) / 256, 256>>>(W2, (u16*)w2);
    k_wsplit<64, 128><<<(27 * 128 * 64 + 255) / 256, 256>>>(W3, (u16*)w3);
    k_min<<<512, 256>>>(xyz);
    k_codes<<<NPTS / 256, 256>>>(xyz);
    k_scanA<<<4096, 1024>>>();
    k_scanB<<<8, 512>>>();
    k_sumMb<<<1, 32>>>();
    k_scanC<<<4096, 1024>>>();
    k_aggregate<<<NPTS / 256, 256>>>(feat, mask);
    k_vnorm<<<NPTS / 256, 256>>>();
    k_nbr<<<dim3(NN / 128, BB), 128>>>();

    // layer 1: x1(16, fp16) -> h1(32)
    conv_pipe<16, 32, 2, 2><<<BB * 256, 256, sm1>>>((const u16*)x1, (float*)p1,
                                                    (const u16*)w1, b1);
    k_zero_stats<<<1, 128>>>();
    k_stats<32><<<dim3(64, BB), 256>>>((const float*)p1);
    k_finalize<32><<<1, 32>>>(g1, be1);
    k_split<32><<<(NPTS * 8 + 255) / 256, 256>>>((const float*)p1, (u16*)x2);

    // layer 2: x2(32, fp16) -> h2(64)
    conv_pipe<32, 64, 2, 2><<<BB * 256, 256, sm2>>>((const u16*)x2, (float*)p2,
                                                    (const u16*)w2, b2);
    k_zero_stats<<<1, 128>>>();
    k_stats<64><<<dim3(64, BB), 256>>>((const float*)p2);
    k_finalize<64><<<1, 64>>>(g2, be2);
    k_split<64><<<(NPTS * 16 + 255) / 256, 256>>>((const float*)p2, (u16*)x3);

    // layer 3: x3(64, fp16) -> h3(128)
    conv_pipe<64, 128, 4, 1><<<BB * 256, 256, sm3>>>((const u16*)x3, (float*)p3,
                                                     (const u16*)w3, b3);
    k_zero_stats<<<1, 128>>>();
    k_stats<128><<<dim3(64, BB), 256>>>((const float*)p3);
    k_finalize<128><<<1, 128>>>(g3, be3);

    // scatter: out[point] = relu(bn3(h3[inv])) * mask
    k_final<<<(NPTS * 32 + 255) / 256, 256>>>(mask, out);
}